// round 1
// baseline (speedup 1.0000x reference)
#include <cuda_runtime.h>

#define NN 50000
#define NE 800000
#define D  128
#define KH 3

// ---------------- scratch (static device globals; allocation-free) ----------------
__device__ int   g_deg[NN];
__device__ float g_dinv[NN];
__device__ int   g_rowptr[NN + 1];
__device__ int   g_cursor[NN];
__device__ int   g_col[NE];
__device__ float g_H[KH][2][(size_t)NN * D];   // hops 1..3, both input channels (153.6 MB)
__device__ float g_C[2][(size_t)NN * 256];     // combined features per output channel (102.4 MB)

// ---------------- degree / normalization ----------------
__global__ void k_zero() {
    int i = blockIdx.x * blockDim.x + threadIdx.x;
    if (i < NN) g_deg[i] = 0;
}

__global__ void k_count(const int* __restrict__ ei) {
    int e = blockIdx.x * blockDim.x + threadIdx.x;
    if (e < NE) atomicAdd(&g_deg[ei[e]], 1);
}

__global__ void k_dinv() {
    int i = blockIdx.x * blockDim.x + threadIdx.x;
    if (i < NN) {
        int d = g_deg[i];
        g_dinv[i] = (d > 0) ? rsqrtf((float)d) : 0.0f;
    }
}

// single-block scan over degrees -> row_ptr + cursor
__global__ void k_scan() {
    __shared__ int s[1024];
    int t = threadIdx.x;
    const int CH = (NN + 1023) / 1024;  // 49
    int lo = t * CH;
    int hi = lo + CH; if (hi > NN) hi = NN;
    int sum = 0;
    if (lo < NN) for (int i = lo; i < hi; i++) sum += g_deg[i];
    s[t] = sum;
    __syncthreads();
    for (int off = 1; off < 1024; off <<= 1) {
        int v = (t >= off) ? s[t - off] : 0;
        __syncthreads();
        s[t] += v;
        __syncthreads();
    }
    int run = s[t] - sum;  // exclusive prefix
    if (lo < NN) {
        for (int i = lo; i < hi; i++) {
            g_cursor[i] = run;
            run += g_deg[i];
            g_rowptr[i + 1] = run;
        }
    }
    if (t == 0) g_rowptr[0] = 0;
}

__global__ void k_scatter(const int* __restrict__ ei) {
    int e = blockIdx.x * blockDim.x + threadIdx.x;
    if (e < NE) {
        int r = ei[e];
        int p = atomicAdd(&g_cursor[r], 1);
        g_col[p] = ei[NE + e];
    }
}

// ---------------- SpMM: one warp per node, both channels per edge ----------------
__global__ void k_spmm(const float* __restrict__ x, int hop) {
    int gw   = (blockIdx.x * blockDim.x + threadIdx.x) >> 5;
    int lane = threadIdx.x & 31;
    if (gw >= NN) return;

    const float* X0;
    const float* X1;
    if (hop == 0) { X0 = x;              X1 = x + (size_t)NN * D; }
    else          { X0 = g_H[hop - 1][0]; X1 = g_H[hop - 1][1];  }
    float* Y0 = g_H[hop][0];
    float* Y1 = g_H[hop][1];

    int s = g_rowptr[gw];
    int e = g_rowptr[gw + 1];

    float4 a0 = make_float4(0.f, 0.f, 0.f, 0.f);
    float4 a1 = make_float4(0.f, 0.f, 0.f, 0.f);

    int i = s;
    for (; i + 2 <= e; i += 2) {
        int   c0 = g_col[i];
        int   c1 = g_col[i + 1];
        float v0 = g_dinv[c0];
        float v1 = g_dinv[c1];
        float4 q00 = __ldg((const float4*)(X0 + (size_t)c0 * D) + lane);
        float4 q01 = __ldg((const float4*)(X1 + (size_t)c0 * D) + lane);
        float4 q10 = __ldg((const float4*)(X0 + (size_t)c1 * D) + lane);
        float4 q11 = __ldg((const float4*)(X1 + (size_t)c1 * D) + lane);
        a0.x += v0 * q00.x; a0.y += v0 * q00.y; a0.z += v0 * q00.z; a0.w += v0 * q00.w;
        a1.x += v0 * q01.x; a1.y += v0 * q01.y; a1.z += v0 * q01.z; a1.w += v0 * q01.w;
        a0.x += v1 * q10.x; a0.y += v1 * q10.y; a0.z += v1 * q10.z; a0.w += v1 * q10.w;
        a1.x += v1 * q11.x; a1.y += v1 * q11.y; a1.z += v1 * q11.z; a1.w += v1 * q11.w;
    }
    if (i < e) {
        int   c0 = g_col[i];
        float v0 = g_dinv[c0];
        float4 q00 = __ldg((const float4*)(X0 + (size_t)c0 * D) + lane);
        float4 q01 = __ldg((const float4*)(X1 + (size_t)c0 * D) + lane);
        a0.x += v0 * q00.x; a0.y += v0 * q00.y; a0.z += v0 * q00.z; a0.w += v0 * q00.w;
        a1.x += v0 * q01.x; a1.y += v0 * q01.y; a1.z += v0 * q01.z; a1.w += v0 * q01.w;
    }

    float sc = g_dinv[gw];
    a0.x *= sc; a0.y *= sc; a0.z *= sc; a0.w *= sc;
    a1.x *= sc; a1.y *= sc; a1.z *= sc; a1.w *= sc;
    ((float4*)(Y0 + (size_t)gw * D))[lane] = a0;
    ((float4*)(Y1 + (size_t)gw * D))[lane] = a1;
}

// ---------------- combine: C[i][n, j*128+d] = sum_m params[i,j,m] * H[m][j][n,d] ----------------
__global__ void k_combine(const float* __restrict__ x, const float* __restrict__ params) {
    int t = blockIdx.x * blockDim.x + threadIdx.x;
    if (t >= NN * 64) return;           // NN * IC * (D/4)
    int n   = t >> 6;
    int rem = t & 63;
    int j   = rem >> 5;
    int d4  = rem & 31;

    size_t xoff = ((size_t)j * NN + n) * D + d4 * 4;
    size_t hoff = (size_t)n * D + d4 * 4;

    float4 h0 = __ldg((const float4*)(x + xoff));
    float4 h1 = *(const float4*)&g_H[0][j][hoff];
    float4 h2 = *(const float4*)&g_H[1][j][hoff];
    float4 h3 = *(const float4*)&g_H[2][j][hoff];

#pragma unroll
    for (int i = 0; i < 2; i++) {
        const float* p = params + (i * 2 + j) * (KH + 1);
        float p0 = __ldg(p + 0), p1 = __ldg(p + 1), p2 = __ldg(p + 2), p3 = __ldg(p + 3);
        float4 r;
        r.x = p0 * h0.x + p1 * h1.x + p2 * h2.x + p3 * h3.x;
        r.y = p0 * h0.y + p1 * h1.y + p2 * h2.y + p3 * h3.y;
        r.z = p0 * h0.z + p1 * h1.z + p2 * h2.z + p3 * h3.z;
        r.w = p0 * h0.w + p1 * h1.w + p2 * h2.w + p3 * h3.w;
        *(float4*)&g_C[i][(size_t)n * 256 + j * 128 + d4 * 4] = r;
    }
}

// ---------------- GEMM: out[i] = C[i] (N x 256) @ W[i] (256 x 128) ----------------
__global__ void __launch_bounds__(256) k_gemm(const float* __restrict__ W, float* __restrict__ out) {
    const int i = blockIdx.y;
    const float* A = g_C[i];                          // [N, 256]
    const float* B = W + (size_t)i * 256 * 128;       // [256, 128]
    float* Cout    = out + (size_t)i * NN * 128;

    __shared__ float As[16][132];
    __shared__ float Bs[16][132];

    int tid = threadIdx.x;
    int tx = tid & 15;        // n tile: 8 cols
    int ty = tid >> 4;        // m tile: 8 rows
    int m0 = blockIdx.x * 128;

    float acc[8][8];
#pragma unroll
    for (int u = 0; u < 8; u++)
#pragma unroll
        for (int v = 0; v < 8; v++) acc[u][v] = 0.f;

    for (int kt = 0; kt < 256; kt += 16) {
        // load A tile: 128 x 16 (store transposed)
#pragma unroll
        for (int r = 0; r < 8; r++) {
            int idx = tid + r * 256;
            int m = idx >> 4, k = idx & 15;
            int gm = m0 + m;
            As[k][m] = (gm < NN) ? A[(size_t)gm * 256 + kt + k] : 0.f;
        }
        // load B tile: 16 x 128
#pragma unroll
        for (int r = 0; r < 8; r++) {
            int idx = tid + r * 256;
            int k = idx >> 7, f = idx & 127;
            Bs[k][f] = B[(size_t)(kt + k) * 128 + f];
        }
        __syncthreads();

#pragma unroll
        for (int k = 0; k < 16; k++) {
            float a[8], b[8];
            *(float4*)&a[0] = *(const float4*)&As[k][ty * 8];
            *(float4*)&a[4] = *(const float4*)&As[k][ty * 8 + 4];
            *(float4*)&b[0] = *(const float4*)&Bs[k][tx * 8];
            *(float4*)&b[4] = *(const float4*)&Bs[k][tx * 8 + 4];
#pragma unroll
            for (int u = 0; u < 8; u++)
#pragma unroll
                for (int v = 0; v < 8; v++)
                    acc[u][v] += a[u] * b[v];
        }
        __syncthreads();
    }

#pragma unroll
    for (int u = 0; u < 8; u++) {
        int gm = m0 + ty * 8 + u;
        if (gm < NN) {
            float4 s0 = make_float4(acc[u][0], acc[u][1], acc[u][2], acc[u][3]);
            float4 s1 = make_float4(acc[u][4], acc[u][5], acc[u][6], acc[u][7]);
            *(float4*)&Cout[(size_t)gm * 128 + tx * 8]     = s0;
            *(float4*)&Cout[(size_t)gm * 128 + tx * 8 + 4] = s1;
        }
    }
}

// ---------------- launcher ----------------
extern "C" void kernel_launch(void* const* d_in, const int* in_sizes, int n_in,
                              void* d_out, int out_size) {
    const float* x      = (const float*)d_in[0];   // [2, 50000, 128]
    const int*   ei     = (const int*)  d_in[1];   // [2, 800000]
    const float* W      = (const float*)d_in[2];   // [2, 2, 128, 128]
    const float* params = (const float*)d_in[3];   // [2, 2, 4]
    float* out = (float*)d_out;                    // [2, 50000, 128]

    k_zero   <<<(NN + 255) / 256, 256>>>();
    k_count  <<<(NE + 255) / 256, 256>>>(ei);
    k_dinv   <<<(NN + 255) / 256, 256>>>();
    k_scan   <<<1, 1024>>>();
    k_scatter<<<(NE + 255) / 256, 256>>>(ei);

    for (int h = 0; h < KH; h++)
        k_spmm<<<(NN * 32 + 255) / 256, 256>>>(x, h);

    k_combine<<<(NN * 64 + 255) / 256, 256>>>(x, params);

    dim3 g((NN + 127) / 128, 2);
    k_gemm<<<g, 256>>>(W, out);
}

// round 2
// speedup vs baseline: 1.1898x; 1.1898x over previous
#include <cuda_runtime.h>

#define NN 50000
#define NE 800000
#define D  128
#define KH 3
#define NB ((NN + 255) / 256)   // 196 blocks for scans

// ---------------- scratch (static device globals; allocation-free) ----------------
__device__ int   g_deg[NN];
__device__ float g_dinv[NN];
__device__ int   g_rowptr[NN + 1];
__device__ int   g_cursor[NN];
__device__ int   g_col[NE];
__device__ float g_val[NE];
__device__ int   g_part[NB];
__device__ int   g_poff[NB];
__device__ float g_H[2][2][(size_t)NN * D];    // hops 1..2, both input channels
__device__ float g_C[2][(size_t)NN * 256];     // combined features per output channel

// ---------------- degree / normalization ----------------
__global__ void k_zero() {
    int i = blockIdx.x * blockDim.x + threadIdx.x;
    if (i < NN) g_deg[i] = 0;
}

__global__ void k_count(const int* __restrict__ ei) {
    int e = blockIdx.x * blockDim.x + threadIdx.x;
    if (e < NE) atomicAdd(&g_deg[ei[e]], 1);
}

__global__ void k_dinv() {
    int i = blockIdx.x * blockDim.x + threadIdx.x;
    if (i < NN) {
        int d = g_deg[i];
        g_dinv[i] = (d > 0) ? rsqrtf((float)d) : 0.0f;
    }
}

// ---------------- hierarchical exclusive scan over degrees ----------------
__global__ void k_blocksum() {
    __shared__ int s[256];
    int t = threadIdx.x;
    int i = blockIdx.x * 256 + t;
    s[t] = (i < NN) ? g_deg[i] : 0;
    __syncthreads();
    for (int off = 128; off > 0; off >>= 1) {
        if (t < off) s[t] += s[t + off];
        __syncthreads();
    }
    if (t == 0) g_part[blockIdx.x] = s[0];
}

__global__ void k_scanpart() {
    __shared__ int s[256];
    int t = threadIdx.x;
    int v = (t < NB) ? g_part[t] : 0;
    s[t] = v;
    __syncthreads();
    for (int off = 1; off < 256; off <<= 1) {
        int u = (t >= off) ? s[t - off] : 0;
        __syncthreads();
        s[t] += u;
        __syncthreads();
    }
    if (t < NB) g_poff[t] = s[t] - v;   // exclusive block offset
}

__global__ void k_rowptr() {
    __shared__ int s[256];
    int t = threadIdx.x;
    int i = blockIdx.x * 256 + t;
    int v = (i < NN) ? g_deg[i] : 0;
    s[t] = v;
    __syncthreads();
    for (int off = 1; off < 256; off <<= 1) {
        int u = (t >= off) ? s[t - off] : 0;
        __syncthreads();
        s[t] += u;
        __syncthreads();
    }
    int base = g_poff[blockIdx.x];
    if (i < NN) {
        g_cursor[i]     = base + s[t] - v;
        g_rowptr[i + 1] = base + s[t];
    }
    if (i == 0) g_rowptr[0] = 0;
}

__global__ void k_scatter(const int* __restrict__ ei) {
    int e = blockIdx.x * blockDim.x + threadIdx.x;
    if (e < NE) {
        int r = ei[e];
        int c = ei[NE + e];
        int p = atomicAdd(&g_cursor[r], 1);
        g_col[p] = c;
        g_val[p] = g_dinv[c];
    }
}

// ---------------- SpMM hops 0,1: one warp per node, both channels per edge ----------------
__global__ void k_spmm(const float* __restrict__ x, int hop) {
    int gw   = (blockIdx.x * blockDim.x + threadIdx.x) >> 5;
    int lane = threadIdx.x & 31;
    if (gw >= NN) return;

    const float* X0;
    const float* X1;
    if (hop == 0) { X0 = x;           X1 = x + (size_t)NN * D; }
    else          { X0 = g_H[0][0];   X1 = g_H[0][1];          }
    float* Y0 = g_H[hop][0];
    float* Y1 = g_H[hop][1];

    int s = g_rowptr[gw];
    int e = g_rowptr[gw + 1];

    float4 a0 = make_float4(0.f, 0.f, 0.f, 0.f);
    float4 a1 = make_float4(0.f, 0.f, 0.f, 0.f);

    int i = s;
    for (; i + 2 <= e; i += 2) {
        int   c0 = g_col[i];
        int   c1 = g_col[i + 1];
        float v0 = g_val[i];
        float v1 = g_val[i + 1];
        float4 q00 = __ldg((const float4*)(X0 + (size_t)c0 * D) + lane);
        float4 q01 = __ldg((const float4*)(X1 + (size_t)c0 * D) + lane);
        float4 q10 = __ldg((const float4*)(X0 + (size_t)c1 * D) + lane);
        float4 q11 = __ldg((const float4*)(X1 + (size_t)c1 * D) + lane);
        a0.x += v0 * q00.x; a0.y += v0 * q00.y; a0.z += v0 * q00.z; a0.w += v0 * q00.w;
        a1.x += v0 * q01.x; a1.y += v0 * q01.y; a1.z += v0 * q01.z; a1.w += v0 * q01.w;
        a0.x += v1 * q10.x; a0.y += v1 * q10.y; a0.z += v1 * q10.z; a0.w += v1 * q10.w;
        a1.x += v1 * q11.x; a1.y += v1 * q11.y; a1.z += v1 * q11.z; a1.w += v1 * q11.w;
    }
    if (i < e) {
        int   c0 = g_col[i];
        float v0 = g_val[i];
        float4 q00 = __ldg((const float4*)(X0 + (size_t)c0 * D) + lane);
        float4 q01 = __ldg((const float4*)(X1 + (size_t)c0 * D) + lane);
        a0.x += v0 * q00.x; a0.y += v0 * q00.y; a0.z += v0 * q00.z; a0.w += v0 * q00.w;
        a1.x += v0 * q01.x; a1.y += v0 * q01.y; a1.z += v0 * q01.z; a1.w += v0 * q01.w;
    }

    float sc = g_dinv[gw];
    a0.x *= sc; a0.y *= sc; a0.z *= sc; a0.w *= sc;
    a1.x *= sc; a1.y *= sc; a1.z *= sc; a1.w *= sc;
    ((float4*)(Y0 + (size_t)gw * D))[lane] = a0;
    ((float4*)(Y1 + (size_t)gw * D))[lane] = a1;
}

// ---------------- SpMM hop 2 fused with hop-combine: writes g_C directly ----------------
__global__ void k_spmm_combine(const float* __restrict__ x, const float* __restrict__ params) {
    int gw   = (blockIdx.x * blockDim.x + threadIdx.x) >> 5;
    int lane = threadIdx.x & 31;
    if (gw >= NN) return;

    const float* X0 = g_H[1][0];
    const float* X1 = g_H[1][1];

    int s = g_rowptr[gw];
    int e = g_rowptr[gw + 1];

    float4 a0 = make_float4(0.f, 0.f, 0.f, 0.f);
    float4 a1 = make_float4(0.f, 0.f, 0.f, 0.f);

    int i = s;
    for (; i + 2 <= e; i += 2) {
        int   c0 = g_col[i];
        int   c1 = g_col[i + 1];
        float v0 = g_val[i];
        float v1 = g_val[i + 1];
        float4 q00 = __ldg((const float4*)(X0 + (size_t)c0 * D) + lane);
        float4 q01 = __ldg((const float4*)(X1 + (size_t)c0 * D) + lane);
        float4 q10 = __ldg((const float4*)(X0 + (size_t)c1 * D) + lane);
        float4 q11 = __ldg((const float4*)(X1 + (size_t)c1 * D) + lane);
        a0.x += v0 * q00.x; a0.y += v0 * q00.y; a0.z += v0 * q00.z; a0.w += v0 * q00.w;
        a1.x += v0 * q01.x; a1.y += v0 * q01.y; a1.z += v0 * q01.z; a1.w += v0 * q01.w;
        a0.x += v1 * q10.x; a0.y += v1 * q10.y; a0.z += v1 * q10.z; a0.w += v1 * q10.w;
        a1.x += v1 * q11.x; a1.y += v1 * q11.y; a1.z += v1 * q11.z; a1.w += v1 * q11.w;
    }
    if (i < e) {
        int   c0 = g_col[i];
        float v0 = g_val[i];
        float4 q00 = __ldg((const float4*)(X0 + (size_t)c0 * D) + lane);
        float4 q01 = __ldg((const float4*)(X1 + (size_t)c0 * D) + lane);
        a0.x += v0 * q00.x; a0.y += v0 * q00.y; a0.z += v0 * q00.z; a0.w += v0 * q00.w;
        a1.x += v0 * q01.x; a1.y += v0 * q01.y; a1.z += v0 * q01.z; a1.w += v0 * q01.w;
    }

    float sc = g_dinv[gw];
    a0.x *= sc; a0.y *= sc; a0.z *= sc; a0.w *= sc;   // hop-3 row, channel 0
    a1.x *= sc; a1.y *= sc; a1.z *= sc; a1.w *= sc;   // hop-3 row, channel 1

    // gather the other hop rows for this node
    size_t hoff = (size_t)gw * D;
    float4 x0 = __ldg((const float4*)(x + hoff) + lane);
    float4 x1 = __ldg((const float4*)(x + (size_t)NN * D + hoff) + lane);
    float4 h10 = *((const float4*)(g_H[0][0] + hoff) + lane);
    float4 h11 = *((const float4*)(g_H[0][1] + hoff) + lane);
    float4 h20 = *((const float4*)(g_H[1][0] + hoff) + lane);
    float4 h21 = *((const float4*)(g_H[1][1] + hoff) + lane);

#pragma unroll
    for (int ic = 0; ic < 2; ic++) {
#pragma unroll
        for (int j = 0; j < 2; j++) {
            const float* p = params + (ic * 2 + j) * (KH + 1);
            float p0 = __ldg(p + 0), p1 = __ldg(p + 1), p2 = __ldg(p + 2), p3 = __ldg(p + 3);
            float4 h0 = j ? x1  : x0;
            float4 h1 = j ? h11 : h10;
            float4 h2 = j ? h21 : h20;
            float4 h3 = j ? a1  : a0;
            float4 r;
            r.x = p0 * h0.x + p1 * h1.x + p2 * h2.x + p3 * h3.x;
            r.y = p0 * h0.y + p1 * h1.y + p2 * h2.y + p3 * h3.y;
            r.z = p0 * h0.z + p1 * h1.z + p2 * h2.z + p3 * h3.z;
            r.w = p0 * h0.w + p1 * h1.w + p2 * h2.w + p3 * h3.w;
            *((float4*)(g_C[ic] + (size_t)gw * 256 + j * 128) + lane) = r;
        }
    }
}

// ---------------- GEMM: out[i] = C[i] (N x 256) @ W[i] (256 x 128) ----------------
__global__ void __launch_bounds__(256) k_gemm(const float* __restrict__ W, float* __restrict__ out) {
    const int i = blockIdx.y;
    const float* A = g_C[i];                          // [N, 256]
    const float* B = W + (size_t)i * 256 * 128;       // [256, 128]
    float* Cout    = out + (size_t)i * NN * 128;

    __shared__ float As[16][132];
    __shared__ float Bs[16][132];

    int tid = threadIdx.x;
    int tx = tid & 15;        // n tile: 8 cols
    int ty = tid >> 4;        // m tile: 8 rows
    int m0 = blockIdx.x * 128;

    float acc[8][8];
#pragma unroll
    for (int u = 0; u < 8; u++)
#pragma unroll
        for (int v = 0; v < 8; v++) acc[u][v] = 0.f;

    for (int kt = 0; kt < 256; kt += 16) {
#pragma unroll
        for (int r = 0; r < 8; r++) {
            int idx = tid + r * 256;
            int m = idx >> 4, k = idx & 15;
            int gm = m0 + m;
            As[k][m] = (gm < NN) ? A[(size_t)gm * 256 + kt + k] : 0.f;
        }
#pragma unroll
        for (int r = 0; r < 8; r++) {
            int idx = tid + r * 256;
            int k = idx >> 7, f = idx & 127;
            Bs[k][f] = B[(size_t)(kt + k) * 128 + f];
        }
        __syncthreads();

#pragma unroll
        for (int k = 0; k < 16; k++) {
            float a[8], b[8];
            *(float4*)&a[0] = *(const float4*)&As[k][ty * 8];
            *(float4*)&a[4] = *(const float4*)&As[k][ty * 8 + 4];
            *(float4*)&b[0] = *(const float4*)&Bs[k][tx * 8];
            *(float4*)&b[4] = *(const float4*)&Bs[k][tx * 8 + 4];
#pragma unroll
            for (int u = 0; u < 8; u++)
#pragma unroll
                for (int v = 0; v < 8; v++)
                    acc[u][v] += a[u] * b[v];
        }
        __syncthreads();
    }

#pragma unroll
    for (int u = 0; u < 8; u++) {
        int gm = m0 + ty * 8 + u;
        if (gm < NN) {
            float4 s0 = make_float4(acc[u][0], acc[u][1], acc[u][2], acc[u][3]);
            float4 s1 = make_float4(acc[u][4], acc[u][5], acc[u][6], acc[u][7]);
            *(float4*)&Cout[(size_t)gm * 128 + tx * 8]     = s0;
            *(float4*)&Cout[(size_t)gm * 128 + tx * 8 + 4] = s1;
        }
    }
}

// ---------------- launcher ----------------
extern "C" void kernel_launch(void* const* d_in, const int* in_sizes, int n_in,
                              void* d_out, int out_size) {
    const float* x      = (const float*)d_in[0];   // [2, 50000, 128]
    const int*   ei     = (const int*)  d_in[1];   // [2, 800000]
    const float* W      = (const float*)d_in[2];   // [2, 2, 128, 128]
    const float* params = (const float*)d_in[3];   // [2, 2, 4]
    float* out = (float*)d_out;                    // [2, 50000, 128]

    k_zero    <<<(NN + 255) / 256, 256>>>();
    k_count   <<<(NE + 255) / 256, 256>>>(ei);
    k_dinv    <<<(NN + 255) / 256, 256>>>();
    k_blocksum<<<NB, 256>>>();
    k_scanpart<<<1, 256>>>();
    k_rowptr  <<<NB, 256>>>();
    k_scatter <<<(NE + 255) / 256, 256>>>(ei);

    k_spmm<<<(NN * 32 + 255) / 256, 256>>>(x, 0);
    k_spmm<<<(NN * 32 + 255) / 256, 256>>>(x, 1);
    k_spmm_combine<<<(NN * 32 + 255) / 256, 256>>>(x, params);

    dim3 g((NN + 127) / 128, 2);
    k_gemm<<<g, 256>>>(W, out);
}

// round 3
// speedup vs baseline: 1.2124x; 1.0189x over previous
#include <cuda_runtime.h>

#define NN 50000
#define NE 800000
#define D  128
#define KH 3
#define NB ((NN + 255) / 256)   // 196 blocks for scans

// ---------------- scratch (static device globals; allocation-free) ----------------
__device__ int   g_deg[NN];
__device__ float g_dinv[NN];
__device__ int   g_rowptr[NN + 1];
__device__ int   g_cursor[NN];
__device__ int   g_col[NE];
__device__ float g_val[NE];
__device__ int   g_part[NB];
__device__ int   g_poff[NB];
__device__ float g_H[2][2][(size_t)NN * D];    // hops 1..2, both input channels
__device__ float g_C[2][(size_t)NN * 256];     // combined features per output channel

// ---------------- f32x2 packed-FMA helpers ----------------
__device__ __forceinline__ void fma2(unsigned long long& d, unsigned long long a, unsigned long long b) {
    asm("fma.rn.f32x2 %0, %1, %2, %0;" : "+l"(d) : "l"(a), "l"(b));
}
__device__ __forceinline__ unsigned long long dup2(float a) {
    unsigned long long r;
    asm("mov.b64 %0, {%1, %1};" : "=l"(r) : "f"(a));
    return r;
}

// ---------------- degree / normalization ----------------
__global__ void k_zero() {
    int i = blockIdx.x * blockDim.x + threadIdx.x;
    if (i < NN) g_deg[i] = 0;
}

__global__ void k_count(const int* __restrict__ ei) {
    int e = blockIdx.x * blockDim.x + threadIdx.x;
    if (e < NE) atomicAdd(&g_deg[ei[e]], 1);
}

// fused: dinv + per-block degree sums
__global__ void k_dinv_blocksum() {
    __shared__ int s[256];
    int t = threadIdx.x;
    int i = blockIdx.x * 256 + t;
    int d = (i < NN) ? g_deg[i] : 0;
    if (i < NN) g_dinv[i] = (d > 0) ? rsqrtf((float)d) : 0.0f;
    s[t] = d;
    __syncthreads();
    for (int off = 128; off > 0; off >>= 1) {
        if (t < off) s[t] += s[t + off];
        __syncthreads();
    }
    if (t == 0) g_part[blockIdx.x] = s[0];
}

__global__ void k_scanpart() {
    __shared__ int s[256];
    int t = threadIdx.x;
    int v = (t < NB) ? g_part[t] : 0;
    s[t] = v;
    __syncthreads();
    for (int off = 1; off < 256; off <<= 1) {
        int u = (t >= off) ? s[t - off] : 0;
        __syncthreads();
        s[t] += u;
        __syncthreads();
    }
    if (t < NB) g_poff[t] = s[t] - v;   // exclusive block offset
}

__global__ void k_rowptr() {
    __shared__ int s[256];
    int t = threadIdx.x;
    int i = blockIdx.x * 256 + t;
    int v = (i < NN) ? g_deg[i] : 0;
    s[t] = v;
    __syncthreads();
    for (int off = 1; off < 256; off <<= 1) {
        int u = (t >= off) ? s[t - off] : 0;
        __syncthreads();
        s[t] += u;
        __syncthreads();
    }
    int base = g_poff[blockIdx.x];
    if (i < NN) {
        g_cursor[i]     = base + s[t] - v;
        g_rowptr[i + 1] = base + s[t];
    }
    if (i == 0) g_rowptr[0] = 0;
}

__global__ void k_scatter(const int* __restrict__ ei) {
    int e = blockIdx.x * blockDim.x + threadIdx.x;
    if (e < NE) {
        int r = ei[e];
        int c = ei[NE + e];
        int p = atomicAdd(&g_cursor[r], 1);
        g_col[p] = c;
        g_val[p] = g_dinv[c];
    }
}

// ---------------- SpMM hops 0,1: one warp per node, both channels per edge ----------------
__global__ void k_spmm(const float* __restrict__ x, int hop) {
    int gw   = (blockIdx.x * blockDim.x + threadIdx.x) >> 5;
    int lane = threadIdx.x & 31;
    if (gw >= NN) return;

    const float* X0;
    const float* X1;
    if (hop == 0) { X0 = x;           X1 = x + (size_t)NN * D; }
    else          { X0 = g_H[0][0];   X1 = g_H[0][1];          }
    float* Y0 = g_H[hop][0];
    float* Y1 = g_H[hop][1];

    int s = g_rowptr[gw];
    int e = g_rowptr[gw + 1];

    float4 a0 = make_float4(0.f, 0.f, 0.f, 0.f);
    float4 a1 = make_float4(0.f, 0.f, 0.f, 0.f);

    int i = s;
    for (; i + 2 <= e; i += 2) {
        int   c0 = g_col[i];
        int   c1 = g_col[i + 1];
        float v0 = g_val[i];
        float v1 = g_val[i + 1];
        float4 q00 = __ldg((const float4*)(X0 + (size_t)c0 * D) + lane);
        float4 q01 = __ldg((const float4*)(X1 + (size_t)c0 * D) + lane);
        float4 q10 = __ldg((const float4*)(X0 + (size_t)c1 * D) + lane);
        float4 q11 = __ldg((const float4*)(X1 + (size_t)c1 * D) + lane);
        a0.x += v0 * q00.x; a0.y += v0 * q00.y; a0.z += v0 * q00.z; a0.w += v0 * q00.w;
        a1.x += v0 * q01.x; a1.y += v0 * q01.y; a1.z += v0 * q01.z; a1.w += v0 * q01.w;
        a0.x += v1 * q10.x; a0.y += v1 * q10.y; a0.z += v1 * q10.z; a0.w += v1 * q10.w;
        a1.x += v1 * q11.x; a1.y += v1 * q11.y; a1.z += v1 * q11.z; a1.w += v1 * q11.w;
    }
    if (i < e) {
        int   c0 = g_col[i];
        float v0 = g_val[i];
        float4 q00 = __ldg((const float4*)(X0 + (size_t)c0 * D) + lane);
        float4 q01 = __ldg((const float4*)(X1 + (size_t)c0 * D) + lane);
        a0.x += v0 * q00.x; a0.y += v0 * q00.y; a0.z += v0 * q00.z; a0.w += v0 * q00.w;
        a1.x += v0 * q01.x; a1.y += v0 * q01.y; a1.z += v0 * q01.z; a1.w += v0 * q01.w;
    }

    float sc = g_dinv[gw];
    a0.x *= sc; a0.y *= sc; a0.z *= sc; a0.w *= sc;
    a1.x *= sc; a1.y *= sc; a1.z *= sc; a1.w *= sc;
    ((float4*)(Y0 + (size_t)gw * D))[lane] = a0;
    ((float4*)(Y1 + (size_t)gw * D))[lane] = a1;
}

// ---------------- SpMM hop 2 fused with hop-combine: writes g_C directly ----------------
__global__ void k_spmm_combine(const float* __restrict__ x, const float* __restrict__ params) {
    int gw   = (blockIdx.x * blockDim.x + threadIdx.x) >> 5;
    int lane = threadIdx.x & 31;
    if (gw >= NN) return;

    const float* X0 = g_H[1][0];
    const float* X1 = g_H[1][1];

    int s = g_rowptr[gw];
    int e = g_rowptr[gw + 1];

    float4 a0 = make_float4(0.f, 0.f, 0.f, 0.f);
    float4 a1 = make_float4(0.f, 0.f, 0.f, 0.f);

    int i = s;
    for (; i + 2 <= e; i += 2) {
        int   c0 = g_col[i];
        int   c1 = g_col[i + 1];
        float v0 = g_val[i];
        float v1 = g_val[i + 1];
        float4 q00 = __ldg((const float4*)(X0 + (size_t)c0 * D) + lane);
        float4 q01 = __ldg((const float4*)(X1 + (size_t)c0 * D) + lane);
        float4 q10 = __ldg((const float4*)(X0 + (size_t)c1 * D) + lane);
        float4 q11 = __ldg((const float4*)(X1 + (size_t)c1 * D) + lane);
        a0.x += v0 * q00.x; a0.y += v0 * q00.y; a0.z += v0 * q00.z; a0.w += v0 * q00.w;
        a1.x += v0 * q01.x; a1.y += v0 * q01.y; a1.z += v0 * q01.z; a1.w += v0 * q01.w;
        a0.x += v1 * q10.x; a0.y += v1 * q10.y; a0.z += v1 * q10.z; a0.w += v1 * q10.w;
        a1.x += v1 * q11.x; a1.y += v1 * q11.y; a1.z += v1 * q11.z; a1.w += v1 * q11.w;
    }
    if (i < e) {
        int   c0 = g_col[i];
        float v0 = g_val[i];
        float4 q00 = __ldg((const float4*)(X0 + (size_t)c0 * D) + lane);
        float4 q01 = __ldg((const float4*)(X1 + (size_t)c0 * D) + lane);
        a0.x += v0 * q00.x; a0.y += v0 * q00.y; a0.z += v0 * q00.z; a0.w += v0 * q00.w;
        a1.x += v0 * q01.x; a1.y += v0 * q01.y; a1.z += v0 * q01.z; a1.w += v0 * q01.w;
    }

    float sc = g_dinv[gw];
    a0.x *= sc; a0.y *= sc; a0.z *= sc; a0.w *= sc;   // hop-3 row, channel 0
    a1.x *= sc; a1.y *= sc; a1.z *= sc; a1.w *= sc;   // hop-3 row, channel 1

    size_t hoff = (size_t)gw * D;
    float4 x0  = __ldg((const float4*)(x + hoff) + lane);
    float4 x1  = __ldg((const float4*)(x + (size_t)NN * D + hoff) + lane);
    float4 h10 = *((const float4*)(g_H[0][0] + hoff) + lane);
    float4 h11 = *((const float4*)(g_H[0][1] + hoff) + lane);
    float4 h20 = *((const float4*)(g_H[1][0] + hoff) + lane);
    float4 h21 = *((const float4*)(g_H[1][1] + hoff) + lane);

#pragma unroll
    for (int ic = 0; ic < 2; ic++) {
#pragma unroll
        for (int j = 0; j < 2; j++) {
            const float* p = params + (ic * 2 + j) * (KH + 1);
            float p0 = __ldg(p + 0), p1 = __ldg(p + 1), p2 = __ldg(p + 2), p3 = __ldg(p + 3);
            float4 h0 = j ? x1  : x0;
            float4 h1 = j ? h11 : h10;
            float4 h2 = j ? h21 : h20;
            float4 h3 = j ? a1  : a0;
            float4 r;
            r.x = p0 * h0.x + p1 * h1.x + p2 * h2.x + p3 * h3.x;
            r.y = p0 * h0.y + p1 * h1.y + p2 * h2.y + p3 * h3.y;
            r.z = p0 * h0.z + p1 * h1.z + p2 * h2.z + p3 * h3.z;
            r.w = p0 * h0.w + p1 * h1.w + p2 * h2.w + p3 * h3.w;
            *((float4*)(g_C[ic] + (size_t)gw * 256 + j * 128) + lane) = r;
        }
    }
}

// ---------------- GEMM (f32x2 packed FMA): out[i] = C[i] (N x 256) @ W[i] (256 x 128) ----------------
__global__ void __launch_bounds__(256) k_gemm(const float* __restrict__ W, float* __restrict__ out) {
    const int i = blockIdx.y;
    const float* A = g_C[i];                          // [N, 256]
    const float* B = W + (size_t)i * 256 * 128;       // [256, 128]
    float* Cout    = out + (size_t)i * NN * 128;

    __shared__ float As[16][132];   // row stride 528 B (16B multiple)
    __shared__ float Bs[16][132];

    int tid = threadIdx.x;
    int tx = tid & 15;        // n tile: 8 cols
    int ty = tid >> 4;        // m tile: 8 rows
    int m0 = blockIdx.x * 128;

    unsigned long long acc2[8][4];
#pragma unroll
    for (int u = 0; u < 8; u++)
#pragma unroll
        for (int v = 0; v < 4; v++) acc2[u][v] = 0ull;

    // tile-load lambda targets (register staging for double buffer)
    float ra[8], rb[8];

    // prologue: load tile 0 into regs, store to smem
#pragma unroll
    for (int r = 0; r < 8; r++) {
        int idx = tid + r * 256;
        int m = idx >> 4, k = idx & 15;
        int gm = m0 + m;
        ra[r] = (gm < NN) ? A[(size_t)gm * 256 + k] : 0.f;
        int kb = idx >> 7, f = idx & 127;
        rb[r] = B[(size_t)kb * 128 + f];
    }
#pragma unroll
    for (int r = 0; r < 8; r++) {
        int idx = tid + r * 256;
        As[idx & 15][idx >> 4] = ra[r];
        Bs[idx >> 7][idx & 127] = rb[r];
    }
    __syncthreads();

    for (int kt = 0; kt < 256; kt += 16) {
        // prefetch next tile into registers (overlaps with compute)
        if (kt + 16 < 256) {
#pragma unroll
            for (int r = 0; r < 8; r++) {
                int idx = tid + r * 256;
                int m = idx >> 4, k = idx & 15;
                int gm = m0 + m;
                ra[r] = (gm < NN) ? A[(size_t)gm * 256 + kt + 16 + k] : 0.f;
                int kb = idx >> 7, f = idx & 127;
                rb[r] = B[(size_t)(kt + 16 + kb) * 128 + f];
            }
        }

#pragma unroll
        for (int k = 0; k < 16; k++) {
            float a[8];
            *(float4*)&a[0] = *(const float4*)&As[k][ty * 8];
            *(float4*)&a[4] = *(const float4*)&As[k][ty * 8 + 4];
            // b pairs read directly as 64-bit packed values (free packing)
            ulonglong2 bb0 = *(const ulonglong2*)&Bs[k][tx * 8];
            ulonglong2 bb1 = *(const ulonglong2*)&Bs[k][tx * 8 + 4];
            unsigned long long b2[4] = {bb0.x, bb0.y, bb1.x, bb1.y};
#pragma unroll
            for (int u = 0; u < 8; u++) {
                unsigned long long a2 = dup2(a[u]);
#pragma unroll
                for (int v = 0; v < 4; v++)
                    fma2(acc2[u][v], a2, b2[v]);
            }
        }
        __syncthreads();

        if (kt + 16 < 256) {
#pragma unroll
            for (int r = 0; r < 8; r++) {
                int idx = tid + r * 256;
                As[idx & 15][idx >> 4] = ra[r];
                Bs[idx >> 7][idx & 127] = rb[r];
            }
            __syncthreads();
        }
    }

#pragma unroll
    for (int u = 0; u < 8; u++) {
        int gm = m0 + ty * 8 + u;
        if (gm < NN) {
            ulonglong2 s0, s1;
            s0.x = acc2[u][0]; s0.y = acc2[u][1];
            s1.x = acc2[u][2]; s1.y = acc2[u][3];
            *(ulonglong2*)&Cout[(size_t)gm * 128 + tx * 8]     = s0;
            *(ulonglong2*)&Cout[(size_t)gm * 128 + tx * 8 + 4] = s1;
        }
    }
}

// ---------------- launcher ----------------
extern "C" void kernel_launch(void* const* d_in, const int* in_sizes, int n_in,
                              void* d_out, int out_size) {
    const float* x      = (const float*)d_in[0];   // [2, 50000, 128]
    const int*   ei     = (const int*)  d_in[1];   // [2, 800000]
    const float* W      = (const float*)d_in[2];   // [2, 2, 128, 128]
    const float* params = (const float*)d_in[3];   // [2, 2, 4]
    float* out = (float*)d_out;                    // [2, 50000, 128]

    k_zero         <<<(NN + 255) / 256, 256>>>();
    k_count        <<<(NE + 255) / 256, 256>>>(ei);
    k_dinv_blocksum<<<NB, 256>>>();
    k_scanpart     <<<1, 256>>>();
    k_rowptr       <<<NB, 256>>>();
    k_scatter      <<<(NE + 255) / 256, 256>>>(ei);

    k_spmm<<<(NN * 32 + 255) / 256, 256>>>(x, 0);
    k_spmm<<<(NN * 32 + 255) / 256, 256>>>(x, 1);
    k_spmm_combine<<<(NN * 32 + 255) / 256, 256>>>(x, params);

    dim3 g((NN + 127) / 128, 2);
    k_gemm<<<g, 256>>>(W, out);
}

// round 4
// speedup vs baseline: 1.2793x; 1.0552x over previous
#include <cuda_runtime.h>

#define NN 50000
#define NE 800000
#define D  128
#define KH 3
#define NB ((NN + 255) / 256)   // 196 scan blocks

// ---------------- scratch ----------------
__device__ int   g_deg[NN];
__device__ float g_dinv[NN];
__device__ int   g_rowptr[NN + 1];
__device__ int   g_cursor[NN];
__device__ int   g_col[NE];
__device__ float g_val[NE];
__device__ volatile int g_flag[NB];   // 0=invalid, 1=aggregate ready, 2=inclusive ready
__device__ int   g_agg[NB];
__device__ int   g_inc[NB];
__device__ float g_H[2][2][(size_t)NN * D];
__device__ float g_C[2][(size_t)NN * 256];

// ---------------- f32x2 helpers ----------------
__device__ __forceinline__ void fma2(unsigned long long& d, unsigned long long a, unsigned long long b) {
    asm("fma.rn.f32x2 %0, %1, %2, %0;" : "+l"(d) : "l"(a), "l"(b));
}
__device__ __forceinline__ unsigned long long dup2(float a) {
    unsigned long long r;
    asm("mov.b64 %0, {%1, %1};" : "=l"(r) : "f"(a));
    return r;
}
__device__ __forceinline__ void unpack2(float& lo, float& hi, unsigned long long v) {
    asm("mov.b64 {%0, %1}, %2;" : "=f"(lo), "=f"(hi) : "l"(v));
}

// ---------------- count degrees (also resets scan flags) ----------------
__global__ void k_count(const int* __restrict__ ei) {
    int e = blockIdx.x * blockDim.x + threadIdx.x;
    if (e < NB) g_flag[e] = 0;          // reset lookback state for this launch
    if (e < NE) atomicAdd(&g_deg[ei[e]], 1);
}

// ---------------- single-kernel scan: deg -> rowptr, cursor, dinv (decoupled lookback) ----------------
__global__ void __launch_bounds__(256) k_scan() {
    __shared__ int s[256];
    __shared__ int s_base;
    int t   = threadIdx.x;
    int bid = blockIdx.x;
    int i   = bid * 256 + t;
    int d   = (i < NN) ? g_deg[i] : 0;
    if (i < NN) g_dinv[i] = (d > 0) ? rsqrtf((float)d) : 0.0f;

    // inclusive block scan
    s[t] = d;
    __syncthreads();
#pragma unroll
    for (int off = 1; off < 256; off <<= 1) {
        int u = (t >= off) ? s[t - off] : 0;
        __syncthreads();
        s[t] += u;
        __syncthreads();
    }
    int agg = s[255];

    if (t == 0) {
        if (bid == 0) {
            g_inc[0] = agg;
            __threadfence();
            g_flag[0] = 2;
            s_base = 0;
        } else {
            g_agg[bid] = agg;
            __threadfence();
            g_flag[bid] = 1;
            // lookback
            int base = 0;
            int p = bid - 1;
            while (p >= 0) {
                int f;
                do { f = g_flag[p]; } while (f == 0);
                __threadfence();
                if (f == 2) { base += g_inc[p]; break; }
                base += g_agg[p];
                p--;
            }
            g_inc[bid] = base + agg;
            __threadfence();
            g_flag[bid] = 2;
            s_base = base;
        }
    }
    __syncthreads();
    int base = s_base;

    if (i < NN) {
        g_cursor[i]     = base + s[t] - d;
        g_rowptr[i + 1] = base + s[t];
    }
    if (i == 0) g_rowptr[0] = 0;
}

__global__ void k_scatter(const int* __restrict__ ei) {
    int e = blockIdx.x * blockDim.x + threadIdx.x;
    if (e < NE) {
        int r = ei[e];
        int c = ei[NE + e];
        int p = atomicAdd(&g_cursor[r], 1);
        g_col[p] = c;
        g_val[p] = g_dinv[c];
    }
}

// ---------------- SpMM hops 0,1: one warp per node ----------------
__global__ void __launch_bounds__(256) k_spmm(const float* __restrict__ x, int hop) {
    int gw   = (blockIdx.x * blockDim.x + threadIdx.x) >> 5;
    int lane = threadIdx.x & 31;
    if (gw >= NN) return;

    const float* X0;
    const float* X1;
    if (hop == 0) { X0 = x;         X1 = x + (size_t)NN * D; }
    else          { X0 = g_H[0][0]; X1 = g_H[0][1];          }
    float* Y0 = g_H[hop][0];
    float* Y1 = g_H[hop][1];

    int s = g_rowptr[gw];
    int e = g_rowptr[gw + 1];

    float4 a0 = make_float4(0.f, 0.f, 0.f, 0.f);
    float4 a1 = make_float4(0.f, 0.f, 0.f, 0.f);

    int i = s;
    for (; i + 4 <= e; i += 4) {
        int   c0 = g_col[i],     c1 = g_col[i + 1], c2 = g_col[i + 2], c3 = g_col[i + 3];
        float v0 = g_val[i],     v1 = g_val[i + 1], v2 = g_val[i + 2], v3 = g_val[i + 3];
        float4 q00 = __ldg((const float4*)(X0 + (size_t)c0 * D) + lane);
        float4 q01 = __ldg((const float4*)(X1 + (size_t)c0 * D) + lane);
        float4 q10 = __ldg((const float4*)(X0 + (size_t)c1 * D) + lane);
        float4 q11 = __ldg((const float4*)(X1 + (size_t)c1 * D) + lane);
        float4 q20 = __ldg((const float4*)(X0 + (size_t)c2 * D) + lane);
        float4 q21 = __ldg((const float4*)(X1 + (size_t)c2 * D) + lane);
        float4 q30 = __ldg((const float4*)(X0 + (size_t)c3 * D) + lane);
        float4 q31 = __ldg((const float4*)(X1 + (size_t)c3 * D) + lane);
        a0.x += v0 * q00.x; a0.y += v0 * q00.y; a0.z += v0 * q00.z; a0.w += v0 * q00.w;
        a1.x += v0 * q01.x; a1.y += v0 * q01.y; a1.z += v0 * q01.z; a1.w += v0 * q01.w;
        a0.x += v1 * q10.x; a0.y += v1 * q10.y; a0.z += v1 * q10.z; a0.w += v1 * q10.w;
        a1.x += v1 * q11.x; a1.y += v1 * q11.y; a1.z += v1 * q11.z; a1.w += v1 * q11.w;
        a0.x += v2 * q20.x; a0.y += v2 * q20.y; a0.z += v2 * q20.z; a0.w += v2 * q20.w;
        a1.x += v2 * q21.x; a1.y += v2 * q21.y; a1.z += v2 * q21.z; a1.w += v2 * q21.w;
        a0.x += v3 * q30.x; a0.y += v3 * q30.y; a0.z += v3 * q30.z; a0.w += v3 * q30.w;
        a1.x += v3 * q31.x; a1.y += v3 * q31.y; a1.z += v3 * q31.z; a1.w += v3 * q31.w;
    }
    for (; i < e; i++) {
        int   c0 = g_col[i];
        float v0 = g_val[i];
        float4 q00 = __ldg((const float4*)(X0 + (size_t)c0 * D) + lane);
        float4 q01 = __ldg((const float4*)(X1 + (size_t)c0 * D) + lane);
        a0.x += v0 * q00.x; a0.y += v0 * q00.y; a0.z += v0 * q00.z; a0.w += v0 * q00.w;
        a1.x += v0 * q01.x; a1.y += v0 * q01.y; a1.z += v0 * q01.z; a1.w += v0 * q01.w;
    }

    float sc = g_dinv[gw];
    a0.x *= sc; a0.y *= sc; a0.z *= sc; a0.w *= sc;
    a1.x *= sc; a1.y *= sc; a1.z *= sc; a1.w *= sc;
    ((float4*)(Y0 + (size_t)gw * D))[lane] = a0;
    ((float4*)(Y1 + (size_t)gw * D))[lane] = a1;
}

// ---------------- SpMM hop 2 fused with combine ----------------
__global__ void __launch_bounds__(256) k_spmm_combine(const float* __restrict__ x, const float* __restrict__ params) {
    int gw   = (blockIdx.x * blockDim.x + threadIdx.x) >> 5;
    int lane = threadIdx.x & 31;
    if (gw >= NN) return;

    const float* X0 = g_H[1][0];
    const float* X1 = g_H[1][1];

    int s = g_rowptr[gw];
    int e = g_rowptr[gw + 1];

    float4 a0 = make_float4(0.f, 0.f, 0.f, 0.f);
    float4 a1 = make_float4(0.f, 0.f, 0.f, 0.f);

    int i = s;
    for (; i + 2 <= e; i += 2) {
        int   c0 = g_col[i];
        int   c1 = g_col[i + 1];
        float v0 = g_val[i];
        float v1 = g_val[i + 1];
        float4 q00 = __ldg((const float4*)(X0 + (size_t)c0 * D) + lane);
        float4 q01 = __ldg((const float4*)(X1 + (size_t)c0 * D) + lane);
        float4 q10 = __ldg((const float4*)(X0 + (size_t)c1 * D) + lane);
        float4 q11 = __ldg((const float4*)(X1 + (size_t)c1 * D) + lane);
        a0.x += v0 * q00.x; a0.y += v0 * q00.y; a0.z += v0 * q00.z; a0.w += v0 * q00.w;
        a1.x += v0 * q01.x; a1.y += v0 * q01.y; a1.z += v0 * q01.z; a1.w += v0 * q01.w;
        a0.x += v1 * q10.x; a0.y += v1 * q10.y; a0.z += v1 * q10.z; a0.w += v1 * q10.w;
        a1.x += v1 * q11.x; a1.y += v1 * q11.y; a1.z += v1 * q11.z; a1.w += v1 * q11.w;
    }
    if (i < e) {
        int   c0 = g_col[i];
        float v0 = g_val[i];
        float4 q00 = __ldg((const float4*)(X0 + (size_t)c0 * D) + lane);
        float4 q01 = __ldg((const float4*)(X1 + (size_t)c0 * D) + lane);
        a0.x += v0 * q00.x; a0.y += v0 * q00.y; a0.z += v0 * q00.z; a0.w += v0 * q00.w;
        a1.x += v0 * q01.x; a1.y += v0 * q01.y; a1.z += v0 * q01.z; a1.w += v0 * q01.w;
    }

    float sc = g_dinv[gw];
    a0.x *= sc; a0.y *= sc; a0.z *= sc; a0.w *= sc;
    a1.x *= sc; a1.y *= sc; a1.z *= sc; a1.w *= sc;

    size_t hoff = (size_t)gw * D;
    float4 x0  = __ldg((const float4*)(x + hoff) + lane);
    float4 x1  = __ldg((const float4*)(x + (size_t)NN * D + hoff) + lane);
    float4 h10 = *((const float4*)(g_H[0][0] + hoff) + lane);
    float4 h11 = *((const float4*)(g_H[0][1] + hoff) + lane);
    float4 h20 = *((const float4*)(g_H[1][0] + hoff) + lane);
    float4 h21 = *((const float4*)(g_H[1][1] + hoff) + lane);

#pragma unroll
    for (int ic = 0; ic < 2; ic++) {
#pragma unroll
        for (int j = 0; j < 2; j++) {
            const float* p = params + (ic * 2 + j) * (KH + 1);
            float p0 = __ldg(p + 0), p1 = __ldg(p + 1), p2 = __ldg(p + 2), p3 = __ldg(p + 3);
            float4 h0 = j ? x1  : x0;
            float4 h1 = j ? h11 : h10;
            float4 h2 = j ? h21 : h20;
            float4 h3 = j ? a1  : a0;
            float4 r;
            r.x = p0 * h0.x + p1 * h1.x + p2 * h2.x + p3 * h3.x;
            r.y = p0 * h0.y + p1 * h1.y + p2 * h2.y + p3 * h3.y;
            r.z = p0 * h0.z + p1 * h1.z + p2 * h2.z + p3 * h3.z;
            r.w = p0 * h0.w + p1 * h1.w + p2 * h2.w + p3 * h3.w;
            *((float4*)(g_C[ic] + (size_t)gw * 256 + j * 128) + lane) = r;
        }
    }
}

// ---------------- GEMM: out[i] = C[i] (N x 256) @ W[i] (256 x 128), f32x2, 1 sync/tile ----------------
__global__ void __launch_bounds__(256) k_gemm(const float* __restrict__ W, float* __restrict__ out) {
    const int i = blockIdx.y;
    const float* A = g_C[i];
    const float* B = W + (size_t)i * 256 * 128;
    float* Cout    = out + (size_t)i * NN * 128;

    __shared__ float As[2][16][132];
    __shared__ float Bs[2][16][132];

    int tid = threadIdx.x;
    int tx = tid & 15;        // 8 output cols
    int ty = tid >> 4;        // 8 output rows
    int m0 = blockIdx.x * 128;

    // acc2[u2][v]: packed pair of rows (2*u2, 2*u2+1) at col v
    unsigned long long acc2[4][8];
#pragma unroll
    for (int u = 0; u < 4; u++)
#pragma unroll
        for (int v = 0; v < 8; v++) acc2[u][v] = 0ull;

    float ra[8], rb[8];

    // prologue: tile 0 -> stage 0
#pragma unroll
    for (int r = 0; r < 8; r++) {
        int idx = tid + r * 256;
        int m = idx >> 4, k = idx & 15;
        int gm = m0 + m;
        ra[r] = (gm < NN) ? A[(size_t)gm * 256 + k] : 0.f;
        int kb = idx >> 7, f = idx & 127;
        rb[r] = B[(size_t)kb * 128 + f];
    }
#pragma unroll
    for (int r = 0; r < 8; r++) {
        int idx = tid + r * 256;
        As[0][idx & 15][idx >> 4] = ra[r];
        Bs[0][idx >> 7][idx & 127] = rb[r];
    }
    __syncthreads();

#pragma unroll 1
    for (int kt = 0; kt < 256; kt += 16) {
        int cur = (kt >> 4) & 1;
        int nxt = cur ^ 1;
        bool more = (kt + 16 < 256);

        if (more) {
#pragma unroll
            for (int r = 0; r < 8; r++) {
                int idx = tid + r * 256;
                int m = idx >> 4, k = idx & 15;
                int gm = m0 + m;
                ra[r] = (gm < NN) ? A[(size_t)gm * 256 + kt + 16 + k] : 0.f;
                int kb = idx >> 7, f = idx & 127;
                rb[r] = B[(size_t)(kt + 16 + kb) * 128 + f];
            }
        }

#pragma unroll
        for (int k = 0; k < 16; k++) {
            // A pairs: adjacent rows packed directly from smem
            ulonglong2 aa0 = *(const ulonglong2*)&As[cur][k][ty * 8];
            ulonglong2 aa1 = *(const ulonglong2*)&As[cur][k][ty * 8 + 4];
            unsigned long long a2[4] = {aa0.x, aa0.y, aa1.x, aa1.y};
            float b[8];
            *(float4*)&b[0] = *(const float4*)&Bs[cur][k][tx * 8];
            *(float4*)&b[4] = *(const float4*)&Bs[cur][k][tx * 8 + 4];
#pragma unroll
            for (int v = 0; v < 8; v++) {
                unsigned long long b2 = dup2(b[v]);
#pragma unroll
                for (int u = 0; u < 4; u++)
                    fma2(acc2[u][v], a2[u], b2);
            }
        }

        if (more) {
#pragma unroll
            for (int r = 0; r < 8; r++) {
                int idx = tid + r * 256;
                As[nxt][idx & 15][idx >> 4] = ra[r];
                Bs[nxt][idx >> 7][idx & 127] = rb[r];
            }
        }
        __syncthreads();
    }

    // epilogue: unpack row pairs
#pragma unroll
    for (int u = 0; u < 4; u++) {
        float lo[8], hi[8];
#pragma unroll
        for (int v = 0; v < 8; v++) unpack2(lo[v], hi[v], acc2[u][v]);
        int gm0 = m0 + ty * 8 + u * 2;
        if (gm0 < NN) {
            *(float4*)&Cout[(size_t)gm0 * 128 + tx * 8]     = *(float4*)&lo[0];
            *(float4*)&Cout[(size_t)gm0 * 128 + tx * 8 + 4] = *(float4*)&lo[4];
        }
        if (gm0 + 1 < NN) {
            *(float4*)&Cout[(size_t)(gm0 + 1) * 128 + tx * 8]     = *(float4*)&hi[0];
            *(float4*)&Cout[(size_t)(gm0 + 1) * 128 + tx * 8 + 4] = *(float4*)&hi[4];
        }
    }
}

// ---------------- launcher ----------------
extern "C" void kernel_launch(void* const* d_in, const int* in_sizes, int n_in,
                              void* d_out, int out_size) {
    const float* x      = (const float*)d_in[0];
    const int*   ei     = (const int*)  d_in[1];
    const float* W      = (const float*)d_in[2];
    const float* params = (const float*)d_in[3];
    float* out = (float*)d_out;

    void* degPtr = nullptr;
    cudaGetSymbolAddress(&degPtr, g_deg);
    cudaMemsetAsync(degPtr, 0, NN * sizeof(int));

    k_count  <<<(NE + 255) / 256, 256>>>(ei);
    k_scan   <<<NB, 256>>>();
    k_scatter<<<(NE + 255) / 256, 256>>>(ei);

    k_spmm<<<(NN * 32 + 255) / 256, 256>>>(x, 0);
    k_spmm<<<(NN * 32 + 255) / 256, 256>>>(x, 1);
    k_spmm_combine<<<(NN * 32 + 255) / 256, 256>>>(x, params);

    dim3 g((NN + 127) / 128, 2);
    k_gemm<<<g, 256>>>(W, out);
}

// round 6
// speedup vs baseline: 1.6345x; 1.2777x over previous
#include <cuda_runtime.h>
#include <cuda_bf16.h>
#include <cstdint>

#define NN 50000
#define NE 800000
#define D  128
#define KH 3
#define NB   ((NN + 255) / 256)
#define NT_M ((NN + 127) / 128)

// ---------------- scratch ----------------
__device__ int   g_deg[NN];
__device__ float g_dinv[NN];
__device__ int   g_rowptr[NN + 1];
__device__ int   g_cursor[NN];
__device__ int   g_col[NE];
__device__ float g_val[NE];
__device__ volatile int g_flag[NB];
__device__ int   g_agg[NB];
__device__ int   g_inc[NB];
__device__ float g_H[2][2][(size_t)NN * D];
__device__ __nv_bfloat16 g_Chi[2][(size_t)NN * 256];   // combined features, bf16 hi
__device__ __nv_bfloat16 g_Clo[2][(size_t)NN * 256];   // bf16 residual
__device__ __nv_bfloat16 g_Bp[2][128 * 768];           // B' operand: [f][k'=768]

// ---------------- helpers ----------------
__device__ __forceinline__ uint32_t smem_u32(const void* p) {
    uint32_t a;
    asm("{ .reg .u64 t; cvta.to.shared.u64 t, %1; cvt.u32.u64 %0, t; }" : "=r"(a) : "l"(p));
    return a;
}
__device__ __forceinline__ void ldsm4(uint32_t* r, uint32_t addr) {
    asm volatile("ldmatrix.sync.aligned.m8n8.x4.shared.b16 {%0,%1,%2,%3}, [%4];"
                 : "=r"(r[0]), "=r"(r[1]), "=r"(r[2]), "=r"(r[3]) : "r"(addr));
}
__device__ __forceinline__ void ldsm2(uint32_t* r, uint32_t addr) {
    asm volatile("ldmatrix.sync.aligned.m8n8.x2.shared.b16 {%0,%1}, [%2];"
                 : "=r"(r[0]), "=r"(r[1]) : "r"(addr));
}
__device__ __forceinline__ void mma16816(float* d, const uint32_t* a, const uint32_t* b) {
    asm volatile(
        "mma.sync.aligned.m16n8k16.row.col.f32.bf16.bf16.f32 "
        "{%0,%1,%2,%3}, {%4,%5,%6,%7}, {%8,%9}, {%0,%1,%2,%3};"
        : "+f"(d[0]), "+f"(d[1]), "+f"(d[2]), "+f"(d[3])
        : "r"(a[0]), "r"(a[1]), "r"(a[2]), "r"(a[3]), "r"(b[0]), "r"(b[1]));
}

// ---------------- count degrees (resets lookback flags) ----------------
__global__ void k_count(const int* __restrict__ ei) {
    int e = blockIdx.x * blockDim.x + threadIdx.x;
    if (e < NB) g_flag[e] = 0;
    if (e < NE) atomicAdd(&g_deg[ei[e]], 1);
}

// ---------------- single-kernel scan (decoupled lookback) ----------------
__global__ void __launch_bounds__(256) k_scan() {
    __shared__ int s[256];
    __shared__ int s_base;
    int t   = threadIdx.x;
    int bid = blockIdx.x;
    int i   = bid * 256 + t;
    int d   = (i < NN) ? g_deg[i] : 0;
    if (i < NN) g_dinv[i] = (d > 0) ? rsqrtf((float)d) : 0.0f;

    s[t] = d;
    __syncthreads();
#pragma unroll
    for (int off = 1; off < 256; off <<= 1) {
        int u = (t >= off) ? s[t - off] : 0;
        __syncthreads();
        s[t] += u;
        __syncthreads();
    }
    int agg = s[255];

    if (t == 0) {
        if (bid == 0) {
            g_inc[0] = agg;
            __threadfence();
            g_flag[0] = 2;
            s_base = 0;
        } else {
            g_agg[bid] = agg;
            __threadfence();
            g_flag[bid] = 1;
            int base = 0;
            int p = bid - 1;
            while (p >= 0) {
                int f;
                do { f = g_flag[p]; } while (f == 0);
                __threadfence();
                if (f == 2) { base += g_inc[p]; break; }
                base += g_agg[p];
                p--;
            }
            g_inc[bid] = base + agg;
            __threadfence();
            g_flag[bid] = 2;
            s_base = base;
        }
    }
    __syncthreads();
    int base = s_base;
    if (i < NN) {
        g_cursor[i]     = base + s[t] - d;
        g_rowptr[i + 1] = base + s[t];
    }
    if (i == 0) g_rowptr[0] = 0;
}

__global__ void k_scatter(const int* __restrict__ ei) {
    int e = blockIdx.x * blockDim.x + threadIdx.x;
    if (e < NE) {
        int r = ei[e];
        int c = ei[NE + e];
        int p = atomicAdd(&g_cursor[r], 1);
        g_col[p] = c;
        g_val[p] = g_dinv[c];
    }
}

// ---------------- W split: B'[i][f][k'] (k' = seg*256 + j*128 + d) ----------------
__global__ void k_wsplit(const float* __restrict__ W) {
    int t = blockIdx.x * blockDim.x + threadIdx.x;
    if (t >= 2 * 128 * 768) return;
    int i   = t / (128 * 768);
    int rem = t % (128 * 768);
    int f   = rem / 768;
    int kp  = rem % 768;
    int seg = kp / 256;
    int k   = kp % 256;
    int j   = k / 128;
    int d   = k % 128;
    float w = W[(((size_t)(i * 2 + j) * 128 + d) * 128) + f];
    __nv_bfloat16 hi = __float2bfloat16_rn(w);
    __nv_bfloat16 v  = (seg == 1) ? __float2bfloat16_rn(w - __bfloat162float(hi)) : hi;
    g_Bp[i][(size_t)f * 768 + kp] = v;
}

// ---------------- SpMM hops 0,1 ----------------
__global__ void __launch_bounds__(256) k_spmm(const float* __restrict__ x, int hop) {
    int gw   = (blockIdx.x * blockDim.x + threadIdx.x) >> 5;
    int lane = threadIdx.x & 31;
    if (gw >= NN) return;

    const float* X0;
    const float* X1;
    if (hop == 0) { X0 = x;         X1 = x + (size_t)NN * D; }
    else          { X0 = g_H[0][0]; X1 = g_H[0][1];          }
    float* Y0 = g_H[hop][0];
    float* Y1 = g_H[hop][1];

    int s = g_rowptr[gw];
    int e = g_rowptr[gw + 1];

    float4 a0 = make_float4(0.f, 0.f, 0.f, 0.f);
    float4 a1 = make_float4(0.f, 0.f, 0.f, 0.f);

    int i = s;
    for (; i + 4 <= e; i += 4) {
        int   c0 = g_col[i],     c1 = g_col[i + 1], c2 = g_col[i + 2], c3 = g_col[i + 3];
        float v0 = g_val[i],     v1 = g_val[i + 1], v2 = g_val[i + 2], v3 = g_val[i + 3];
        float4 q00 = __ldg((const float4*)(X0 + (size_t)c0 * D) + lane);
        float4 q01 = __ldg((const float4*)(X1 + (size_t)c0 * D) + lane);
        float4 q10 = __ldg((const float4*)(X0 + (size_t)c1 * D) + lane);
        float4 q11 = __ldg((const float4*)(X1 + (size_t)c1 * D) + lane);
        float4 q20 = __ldg((const float4*)(X0 + (size_t)c2 * D) + lane);
        float4 q21 = __ldg((const float4*)(X1 + (size_t)c2 * D) + lane);
        float4 q30 = __ldg((const float4*)(X0 + (size_t)c3 * D) + lane);
        float4 q31 = __ldg((const float4*)(X1 + (size_t)c3 * D) + lane);
        a0.x += v0 * q00.x; a0.y += v0 * q00.y; a0.z += v0 * q00.z; a0.w += v0 * q00.w;
        a1.x += v0 * q01.x; a1.y += v0 * q01.y; a1.z += v0 * q01.z; a1.w += v0 * q01.w;
        a0.x += v1 * q10.x; a0.y += v1 * q10.y; a0.z += v1 * q10.z; a0.w += v1 * q10.w;
        a1.x += v1 * q11.x; a1.y += v1 * q11.y; a1.z += v1 * q11.z; a1.w += v1 * q11.w;
        a0.x += v2 * q20.x; a0.y += v2 * q20.y; a0.z += v2 * q20.z; a0.w += v2 * q20.w;
        a1.x += v2 * q21.x; a1.y += v2 * q21.y; a1.z += v2 * q21.z; a1.w += v2 * q21.w;
        a0.x += v3 * q30.x; a0.y += v3 * q30.y; a0.z += v3 * q30.z; a0.w += v3 * q30.w;
        a1.x += v3 * q31.x; a1.y += v3 * q31.y; a1.z += v3 * q31.z; a1.w += v3 * q31.w;
    }
    for (; i < e; i++) {
        int   c0 = g_col[i];
        float v0 = g_val[i];
        float4 q00 = __ldg((const float4*)(X0 + (size_t)c0 * D) + lane);
        float4 q01 = __ldg((const float4*)(X1 + (size_t)c0 * D) + lane);
        a0.x += v0 * q00.x; a0.y += v0 * q00.y; a0.z += v0 * q00.z; a0.w += v0 * q00.w;
        a1.x += v0 * q01.x; a1.y += v0 * q01.y; a1.z += v0 * q01.z; a1.w += v0 * q01.w;
    }

    float sc = g_dinv[gw];
    a0.x *= sc; a0.y *= sc; a0.z *= sc; a0.w *= sc;
    a1.x *= sc; a1.y *= sc; a1.z *= sc; a1.w *= sc;
    ((float4*)(Y0 + (size_t)gw * D))[lane] = a0;
    ((float4*)(Y1 + (size_t)gw * D))[lane] = a1;
}

// ---------------- SpMM hop 2 fused with combine; writes bf16 hi/lo C ----------------
__device__ __forceinline__ void store_hilo(__nv_bfloat16* hi_p, __nv_bfloat16* lo_p, float4 r) {
    __nv_bfloat16 h0 = __float2bfloat16_rn(r.x);
    __nv_bfloat16 h1 = __float2bfloat16_rn(r.y);
    __nv_bfloat16 h2 = __float2bfloat16_rn(r.z);
    __nv_bfloat16 h3 = __float2bfloat16_rn(r.w);
    __nv_bfloat16 l0 = __float2bfloat16_rn(r.x - __bfloat162float(h0));
    __nv_bfloat16 l1 = __float2bfloat16_rn(r.y - __bfloat162float(h1));
    __nv_bfloat16 l2 = __float2bfloat16_rn(r.z - __bfloat162float(h2));
    __nv_bfloat16 l3 = __float2bfloat16_rn(r.w - __bfloat162float(h3));
    __nv_bfloat162 hp0(h0, h1), hp1(h2, h3), lp0(l0, l1), lp1(l2, l3);
    ((__nv_bfloat162*)hi_p)[0] = hp0; ((__nv_bfloat162*)hi_p)[1] = hp1;
    ((__nv_bfloat162*)lo_p)[0] = lp0; ((__nv_bfloat162*)lo_p)[1] = lp1;
}

__global__ void __launch_bounds__(256) k_spmm_combine(const float* __restrict__ x, const float* __restrict__ params) {
    int gw   = (blockIdx.x * blockDim.x + threadIdx.x) >> 5;
    int lane = threadIdx.x & 31;
    if (gw >= NN) return;

    const float* X0 = g_H[1][0];
    const float* X1 = g_H[1][1];

    int s = g_rowptr[gw];
    int e = g_rowptr[gw + 1];

    float4 a0 = make_float4(0.f, 0.f, 0.f, 0.f);
    float4 a1 = make_float4(0.f, 0.f, 0.f, 0.f);

    int i = s;
    for (; i + 2 <= e; i += 2) {
        int   c0 = g_col[i];
        int   c1 = g_col[i + 1];
        float v0 = g_val[i];
        float v1 = g_val[i + 1];
        float4 q00 = __ldg((const float4*)(X0 + (size_t)c0 * D) + lane);
        float4 q01 = __ldg((const float4*)(X1 + (size_t)c0 * D) + lane);
        float4 q10 = __ldg((const float4*)(X0 + (size_t)c1 * D) + lane);
        float4 q11 = __ldg((const float4*)(X1 + (size_t)c1 * D) + lane);
        a0.x += v0 * q00.x; a0.y += v0 * q00.y; a0.z += v0 * q00.z; a0.w += v0 * q00.w;
        a1.x += v0 * q01.x; a1.y += v0 * q01.y; a1.z += v0 * q01.z; a1.w += v0 * q01.w;
        a0.x += v1 * q10.x; a0.y += v1 * q10.y; a0.z += v1 * q10.z; a0.w += v1 * q10.w;
        a1.x += v1 * q11.x; a1.y += v1 * q11.y; a1.z += v1 * q11.z; a1.w += v1 * q11.w;
    }
    if (i < e) {
        int   c0 = g_col[i];
        float v0 = g_val[i];
        float4 q00 = __ldg((const float4*)(X0 + (size_t)c0 * D) + lane);
        float4 q01 = __ldg((const float4*)(X1 + (size_t)c0 * D) + lane);
        a0.x += v0 * q00.x; a0.y += v0 * q00.y; a0.z += v0 * q00.z; a0.w += v0 * q00.w;
        a1.x += v0 * q01.x; a1.y += v0 * q01.y; a1.z += v0 * q01.z; a1.w += v0 * q01.w;
    }

    float sc = g_dinv[gw];
    a0.x *= sc; a0.y *= sc; a0.z *= sc; a0.w *= sc;
    a1.x *= sc; a1.y *= sc; a1.z *= sc; a1.w *= sc;

    size_t hoff = (size_t)gw * D;
    float4 x0  = __ldg((const float4*)(x + hoff) + lane);
    float4 x1  = __ldg((const float4*)(x + (size_t)NN * D + hoff) + lane);
    float4 h10 = *((const float4*)(g_H[0][0] + hoff) + lane);
    float4 h11 = *((const float4*)(g_H[0][1] + hoff) + lane);
    float4 h20 = *((const float4*)(g_H[1][0] + hoff) + lane);
    float4 h21 = *((const float4*)(g_H[1][1] + hoff) + lane);

#pragma unroll
    for (int ic = 0; ic < 2; ic++) {
#pragma unroll
        for (int j = 0; j < 2; j++) {
            const float* p = params + (ic * 2 + j) * (KH + 1);
            float p0 = __ldg(p + 0), p1 = __ldg(p + 1), p2 = __ldg(p + 2), p3 = __ldg(p + 3);
            float4 h0 = j ? x1  : x0;
            float4 h1 = j ? h11 : h10;
            float4 h2 = j ? h21 : h20;
            float4 h3 = j ? a1  : a0;
            float4 r;
            r.x = p0 * h0.x + p1 * h1.x + p2 * h2.x + p3 * h3.x;
            r.y = p0 * h0.y + p1 * h1.y + p2 * h2.y + p3 * h3.y;
            r.z = p0 * h0.z + p1 * h1.z + p2 * h2.z + p3 * h3.z;
            r.w = p0 * h0.w + p1 * h1.w + p2 * h2.w + p3 * h3.w;
            size_t off = (size_t)gw * 256 + j * 128 + lane * 4;
            store_hilo(&g_Chi[ic][off], &g_Clo[ic][off], r);
        }
    }
}

// ---------------- mma.sync GEMM: out[ch] (128-tile of N x 128) = C'(Nx768) @ B'^T ----------------
#define SSTRIDE 72   // bf16 elements per smem row (144 B, conflict-free for ldmatrix)

__global__ void __launch_bounds__(256) k_gemm_mma(float* __restrict__ out) {
    const int ch = blockIdx.y;
    const int m0 = blockIdx.x * 128;

    __shared__ __nv_bfloat16 sA[128 * SSTRIDE];
    __shared__ __nv_bfloat16 sB[128 * SSTRIDE];

    int tid  = threadIdx.x;
    int wid  = tid >> 5;
    int lane = tid & 31;
    int wm   = (wid >> 2) * 64;   // warp M offset: 0 or 64
    int wn   = (wid & 3) * 32;    // warp N offset: 0..96

    uint32_t aA = smem_u32(sA);
    uint32_t aB = smem_u32(sB);

    float acc[4][4][4];
#pragma unroll
    for (int mt = 0; mt < 4; mt++)
#pragma unroll
        for (int nt = 0; nt < 4; nt++)
#pragma unroll
            for (int q = 0; q < 4; q++) acc[mt][nt][q] = 0.f;

    // per-lane ldmatrix base addresses (fixed row pattern, column varies per kstep)
    uint32_t aAddrBase = aA + ((wm + (lane & 15)) * SSTRIDE + (lane >> 4) * 8) * 2;
    uint32_t bAddrBase = aB + ((wn + (lane & 7)) * SSTRIDE + ((lane >> 3) & 1) * 8) * 2;

    const __nv_bfloat16* Bsrc = g_Bp[ch];

#pragma unroll 1
    for (int c = 0; c < 12; c++) {
        int seg = c >> 2;
        int kb  = (c & 3) * 64;
        const __nv_bfloat16* Asrc = (seg == 2) ? g_Clo[ch] : g_Chi[ch];

        // stage tiles: 128 rows x 64 bf16 each, 16B per thread x 4 iters
#pragma unroll
        for (int it = 0; it < 4; it++) {
            int u     = tid + it * 256;     // 0..1023
            int row   = u >> 3;
            int inner = u & 7;              // 8 bf16 per 16B unit
            uint4 va = make_uint4(0u, 0u, 0u, 0u);
            int gm = m0 + row;
            if (gm < NN) va = *(const uint4*)(Asrc + (size_t)gm * 256 + kb + inner * 8);
            *(uint4*)(sA + row * SSTRIDE + inner * 8) = va;
            uint4 vb = *(const uint4*)(Bsrc + (size_t)row * 768 + c * 64 + inner * 8);
            *(uint4*)(sB + row * SSTRIDE + inner * 8) = vb;
        }
        __syncthreads();

#pragma unroll
        for (int ks = 0; ks < 4; ks++) {
            uint32_t af[4][4], bf[4][2];
#pragma unroll
            for (int mt = 0; mt < 4; mt++)
                ldsm4(af[mt], aAddrBase + (mt * 16 * SSTRIDE + ks * 16) * 2);
#pragma unroll
            for (int nt = 0; nt < 4; nt++)
                ldsm2(bf[nt], bAddrBase + (nt * 8 * SSTRIDE + ks * 16) * 2);
#pragma unroll
            for (int mt = 0; mt < 4; mt++)
#pragma unroll
                for (int nt = 0; nt < 4; nt++)
                    mma16816(acc[mt][nt], af[mt], bf[nt]);
        }
        __syncthreads();
    }

    // epilogue
    float* Cout = out + (size_t)ch * NN * 128;
    int r0 = lane >> 2;
    int cn = (lane & 3) * 2;
#pragma unroll
    for (int mt = 0; mt < 4; mt++) {
        int gm_a = m0 + wm + mt * 16 + r0;
        int gm_b = gm_a + 8;
#pragma unroll
        for (int nt = 0; nt < 4; nt++) {
            int gn = wn + nt * 8 + cn;
            if (gm_a < NN)
                *(float2*)&Cout[(size_t)gm_a * 128 + gn] = make_float2(acc[mt][nt][0], acc[mt][nt][1]);
            if (gm_b < NN)
                *(float2*)&Cout[(size_t)gm_b * 128 + gn] = make_float2(acc[mt][nt][2], acc[mt][nt][3]);
        }
    }
}

// ---------------- launcher ----------------
extern "C" void kernel_launch(void* const* d_in, const int* in_sizes, int n_in,
                              void* d_out, int out_size) {
    const float* x      = (const float*)d_in[0];
    const int*   ei     = (const int*)  d_in[1];
    const float* W      = (const float*)d_in[2];
    const float* params = (const float*)d_in[3];
    float* out = (float*)d_out;

    void* degPtr = nullptr;
    cudaGetSymbolAddress(&degPtr, g_deg);
    cudaMemsetAsync(degPtr, 0, NN * sizeof(int));

    k_count  <<<(NE + 255) / 256, 256>>>(ei);
    k_scan   <<<NB, 256>>>();
    k_scatter<<<(NE + 255) / 256, 256>>>(ei);
    k_wsplit <<<(2 * 128 * 768 + 255) / 256, 256>>>(W);

    k_spmm<<<(NN * 32 + 255) / 256, 256>>>(x, 0);
    k_spmm<<<(NN * 32 + 255) / 256, 256>>>(x, 1);
    k_spmm_combine<<<(NN * 32 + 255) / 256, 256>>>(x, params);

    dim3 g(NT_M, 2);
    k_gemm_mma<<<g, 256>>>(out);
}

// round 7
// speedup vs baseline: 1.6426x; 1.0049x over previous
#include <cuda_runtime.h>
#include <cuda_bf16.h>
#include <cstdint>

#define NN 50000
#define NE 800000
#define D  128
#define KH 3
#define NB   ((NN + 255) / 256)
#define NT_M ((NN + 127) / 128)

// ---------------- scratch ----------------
__device__ int   g_deg[NN];
__device__ float g_dinv[NN];
__device__ int   g_rowptr[NN + 1];
__device__ int   g_cursor[NN];
__device__ int   g_col[NE];
__device__ float g_val[NE];
__device__ volatile int g_flag[NB];
__device__ int   g_agg[NB];
__device__ int   g_inc[NB];
__device__ float g_H[2][2][(size_t)NN * D];
__device__ __nv_bfloat16 g_Chi[2][(size_t)NN * 256];   // combined features, bf16 hi
__device__ __nv_bfloat16 g_Clo[2][(size_t)NN * 256];   // bf16 residual
__device__ __nv_bfloat16 g_Bp[2][128 * 768];           // B' operand: [f][k'=768]

// ---------------- helpers ----------------
__device__ __forceinline__ uint32_t smem_u32(const void* p) {
    uint32_t a;
    asm("{ .reg .u64 t; cvta.to.shared.u64 t, %1; cvt.u32.u64 %0, t; }" : "=r"(a) : "l"(p));
    return a;
}
__device__ __forceinline__ void ldsm4(uint32_t* r, uint32_t addr) {
    asm volatile("ldmatrix.sync.aligned.m8n8.x4.shared.b16 {%0,%1,%2,%3}, [%4];"
                 : "=r"(r[0]), "=r"(r[1]), "=r"(r[2]), "=r"(r[3]) : "r"(addr));
}
__device__ __forceinline__ void ldsm2(uint32_t* r, uint32_t addr) {
    asm volatile("ldmatrix.sync.aligned.m8n8.x2.shared.b16 {%0,%1}, [%2];"
                 : "=r"(r[0]), "=r"(r[1]) : "r"(addr));
}
__device__ __forceinline__ void mma16816(float* d, const uint32_t* a, const uint32_t* b) {
    asm volatile(
        "mma.sync.aligned.m16n8k16.row.col.f32.bf16.bf16.f32 "
        "{%0,%1,%2,%3}, {%4,%5,%6,%7}, {%8,%9}, {%0,%1,%2,%3};"
        : "+f"(d[0]), "+f"(d[1]), "+f"(d[2]), "+f"(d[3])
        : "r"(a[0]), "r"(a[1]), "r"(a[2]), "r"(a[3]), "r"(b[0]), "r"(b[1]));
}
__device__ __forceinline__ void cp16(uint32_t dst, const void* src, int src_bytes) {
    asm volatile("cp.async.cg.shared.global [%0], [%1], 16, %2;"
                 :: "r"(dst), "l"(src), "r"(src_bytes));
}

// ---------------- count degrees (resets lookback flags) ----------------
__global__ void k_count(const int* __restrict__ ei) {
    int e = blockIdx.x * blockDim.x + threadIdx.x;
    if (e < NB) g_flag[e] = 0;
    if (e < NE) atomicAdd(&g_deg[ei[e]], 1);
}

// ---------------- single-kernel scan (decoupled lookback) ----------------
__global__ void __launch_bounds__(256) k_scan() {
    __shared__ int s[256];
    __shared__ int s_base;
    int t   = threadIdx.x;
    int bid = blockIdx.x;
    int i   = bid * 256 + t;
    int d   = (i < NN) ? g_deg[i] : 0;
    if (i < NN) g_dinv[i] = (d > 0) ? rsqrtf((float)d) : 0.0f;

    s[t] = d;
    __syncthreads();
#pragma unroll
    for (int off = 1; off < 256; off <<= 1) {
        int u = (t >= off) ? s[t - off] : 0;
        __syncthreads();
        s[t] += u;
        __syncthreads();
    }
    int agg = s[255];

    if (t == 0) {
        if (bid == 0) {
            g_inc[0] = agg;
            __threadfence();
            g_flag[0] = 2;
            s_base = 0;
        } else {
            g_agg[bid] = agg;
            __threadfence();
            g_flag[bid] = 1;
            int base = 0;
            int p = bid - 1;
            while (p >= 0) {
                int f;
                do { f = g_flag[p]; } while (f == 0);
                __threadfence();
                if (f == 2) { base += g_inc[p]; break; }
                base += g_agg[p];
                p--;
            }
            g_inc[bid] = base + agg;
            __threadfence();
            g_flag[bid] = 2;
            s_base = base;
        }
    }
    __syncthreads();
    int base = s_base;
    if (i < NN) {
        g_cursor[i]     = base + s[t] - d;
        g_rowptr[i + 1] = base + s[t];
    }
    if (i == 0) g_rowptr[0] = 0;
}

__global__ void k_scatter(const int* __restrict__ ei) {
    int e = blockIdx.x * blockDim.x + threadIdx.x;
    if (e < NE) {
        int r = ei[e];
        int c = ei[NE + e];
        int p = atomicAdd(&g_cursor[r], 1);
        g_col[p] = c;
        g_val[p] = g_dinv[c];
    }
}

// ---------------- W split: B'[i][f][k'] (k' = seg*256 + j*128 + d) ----------------
__global__ void k_wsplit(const float* __restrict__ W) {
    int t = blockIdx.x * blockDim.x + threadIdx.x;
    if (t >= 2 * 128 * 768) return;
    int i   = t / (128 * 768);
    int rem = t % (128 * 768);
    int f   = rem / 768;
    int kp  = rem % 768;
    int seg = kp / 256;
    int k   = kp % 256;
    int j   = k / 128;
    int d   = k % 128;
    float w = W[(((size_t)(i * 2 + j) * 128 + d) * 128) + f];
    __nv_bfloat16 hi = __float2bfloat16_rn(w);
    __nv_bfloat16 v  = (seg == 1) ? __float2bfloat16_rn(w - __bfloat162float(hi)) : hi;
    g_Bp[i][(size_t)f * 768 + kp] = v;
}

// ---------------- SpMM hops 0,1: one warp per node, 128-thread blocks ----------------
__global__ void __launch_bounds__(128) k_spmm(const float* __restrict__ x, int hop) {
    int gw   = (blockIdx.x * blockDim.x + threadIdx.x) >> 5;
    int lane = threadIdx.x & 31;
    if (gw >= NN) return;

    const float* X0;
    const float* X1;
    if (hop == 0) { X0 = x;         X1 = x + (size_t)NN * D; }
    else          { X0 = g_H[0][0]; X1 = g_H[0][1];          }
    float* Y0 = g_H[hop][0];
    float* Y1 = g_H[hop][1];

    int s = g_rowptr[gw];
    int e = g_rowptr[gw + 1];

    float4 a0 = make_float4(0.f, 0.f, 0.f, 0.f);
    float4 a1 = make_float4(0.f, 0.f, 0.f, 0.f);

    int i = s;
    for (; i + 4 <= e; i += 4) {
        int   c0 = g_col[i],     c1 = g_col[i + 1], c2 = g_col[i + 2], c3 = g_col[i + 3];
        float v0 = g_val[i],     v1 = g_val[i + 1], v2 = g_val[i + 2], v3 = g_val[i + 3];
        float4 q00 = __ldg((const float4*)(X0 + (size_t)c0 * D) + lane);
        float4 q01 = __ldg((const float4*)(X1 + (size_t)c0 * D) + lane);
        float4 q10 = __ldg((const float4*)(X0 + (size_t)c1 * D) + lane);
        float4 q11 = __ldg((const float4*)(X1 + (size_t)c1 * D) + lane);
        float4 q20 = __ldg((const float4*)(X0 + (size_t)c2 * D) + lane);
        float4 q21 = __ldg((const float4*)(X1 + (size_t)c2 * D) + lane);
        float4 q30 = __ldg((const float4*)(X0 + (size_t)c3 * D) + lane);
        float4 q31 = __ldg((const float4*)(X1 + (size_t)c3 * D) + lane);
        a0.x += v0 * q00.x; a0.y += v0 * q00.y; a0.z += v0 * q00.z; a0.w += v0 * q00.w;
        a1.x += v0 * q01.x; a1.y += v0 * q01.y; a1.z += v0 * q01.z; a1.w += v0 * q01.w;
        a0.x += v1 * q10.x; a0.y += v1 * q10.y; a0.z += v1 * q10.z; a0.w += v1 * q10.w;
        a1.x += v1 * q11.x; a1.y += v1 * q11.y; a1.z += v1 * q11.z; a1.w += v1 * q11.w;
        a0.x += v2 * q20.x; a0.y += v2 * q20.y; a0.z += v2 * q20.z; a0.w += v2 * q20.w;
        a1.x += v2 * q21.x; a1.y += v2 * q21.y; a1.z += v2 * q21.z; a1.w += v2 * q21.w;
        a0.x += v3 * q30.x; a0.y += v3 * q30.y; a0.z += v3 * q30.z; a0.w += v3 * q30.w;
        a1.x += v3 * q31.x; a1.y += v3 * q31.y; a1.z += v3 * q31.z; a1.w += v3 * q31.w;
    }
    for (; i < e; i++) {
        int   c0 = g_col[i];
        float v0 = g_val[i];
        float4 q00 = __ldg((const float4*)(X0 + (size_t)c0 * D) + lane);
        float4 q01 = __ldg((const float4*)(X1 + (size_t)c0 * D) + lane);
        a0.x += v0 * q00.x; a0.y += v0 * q00.y; a0.z += v0 * q00.z; a0.w += v0 * q00.w;
        a1.x += v0 * q01.x; a1.y += v0 * q01.y; a1.z += v0 * q01.z; a1.w += v0 * q01.w;
    }

    float sc = g_dinv[gw];
    a0.x *= sc; a0.y *= sc; a0.z *= sc; a0.w *= sc;
    a1.x *= sc; a1.y *= sc; a1.z *= sc; a1.w *= sc;
    ((float4*)(Y0 + (size_t)gw * D))[lane] = a0;
    ((float4*)(Y1 + (size_t)gw * D))[lane] = a1;
}

// ---------------- SpMM hop 2 fused with combine; writes bf16 hi/lo C ----------------
__device__ __forceinline__ void store_hilo(__nv_bfloat16* hi_p, __nv_bfloat16* lo_p, float4 r) {
    __nv_bfloat16 h0 = __float2bfloat16_rn(r.x);
    __nv_bfloat16 h1 = __float2bfloat16_rn(r.y);
    __nv_bfloat16 h2 = __float2bfloat16_rn(r.z);
    __nv_bfloat16 h3 = __float2bfloat16_rn(r.w);
    __nv_bfloat16 l0 = __float2bfloat16_rn(r.x - __bfloat162float(h0));
    __nv_bfloat16 l1 = __float2bfloat16_rn(r.y - __bfloat162float(h1));
    __nv_bfloat16 l2 = __float2bfloat16_rn(r.z - __bfloat162float(h2));
    __nv_bfloat16 l3 = __float2bfloat16_rn(r.w - __bfloat162float(h3));
    __nv_bfloat162 hp0(h0, h1), hp1(h2, h3), lp0(l0, l1), lp1(l2, l3);
    ((__nv_bfloat162*)hi_p)[0] = hp0; ((__nv_bfloat162*)hi_p)[1] = hp1;
    ((__nv_bfloat162*)lo_p)[0] = lp0; ((__nv_bfloat162*)lo_p)[1] = lp1;
}

__global__ void __launch_bounds__(128) k_spmm_combine(const float* __restrict__ x, const float* __restrict__ params) {
    int gw   = (blockIdx.x * blockDim.x + threadIdx.x) >> 5;
    int lane = threadIdx.x & 31;
    if (gw >= NN) return;

    const float* X0 = g_H[1][0];
    const float* X1 = g_H[1][1];

    int s = g_rowptr[gw];
    int e = g_rowptr[gw + 1];

    float4 a0 = make_float4(0.f, 0.f, 0.f, 0.f);
    float4 a1 = make_float4(0.f, 0.f, 0.f, 0.f);

    int i = s;
    for (; i + 2 <= e; i += 2) {
        int   c0 = g_col[i];
        int   c1 = g_col[i + 1];
        float v0 = g_val[i];
        float v1 = g_val[i + 1];
        float4 q00 = __ldg((const float4*)(X0 + (size_t)c0 * D) + lane);
        float4 q01 = __ldg((const float4*)(X1 + (size_t)c0 * D) + lane);
        float4 q10 = __ldg((const float4*)(X0 + (size_t)c1 * D) + lane);
        float4 q11 = __ldg((const float4*)(X1 + (size_t)c1 * D) + lane);
        a0.x += v0 * q00.x; a0.y += v0 * q00.y; a0.z += v0 * q00.z; a0.w += v0 * q00.w;
        a1.x += v0 * q01.x; a1.y += v0 * q01.y; a1.z += v0 * q01.z; a1.w += v0 * q01.w;
        a0.x += v1 * q10.x; a0.y += v1 * q10.y; a0.z += v1 * q10.z; a0.w += v1 * q10.w;
        a1.x += v1 * q11.x; a1.y += v1 * q11.y; a1.z += v1 * q11.z; a1.w += v1 * q11.w;
    }
    if (i < e) {
        int   c0 = g_col[i];
        float v0 = g_val[i];
        float4 q00 = __ldg((const float4*)(X0 + (size_t)c0 * D) + lane);
        float4 q01 = __ldg((const float4*)(X1 + (size_t)c0 * D) + lane);
        a0.x += v0 * q00.x; a0.y += v0 * q00.y; a0.z += v0 * q00.z; a0.w += v0 * q00.w;
        a1.x += v0 * q01.x; a1.y += v0 * q01.y; a1.z += v0 * q01.z; a1.w += v0 * q01.w;
    }

    float sc = g_dinv[gw];
    a0.x *= sc; a0.y *= sc; a0.z *= sc; a0.w *= sc;
    a1.x *= sc; a1.y *= sc; a1.z *= sc; a1.w *= sc;

    size_t hoff = (size_t)gw * D;
    float4 x0  = __ldg((const float4*)(x + hoff) + lane);
    float4 x1  = __ldg((const float4*)(x + (size_t)NN * D + hoff) + lane);
    float4 h10 = *((const float4*)(g_H[0][0] + hoff) + lane);
    float4 h11 = *((const float4*)(g_H[0][1] + hoff) + lane);
    float4 h20 = *((const float4*)(g_H[1][0] + hoff) + lane);
    float4 h21 = *((const float4*)(g_H[1][1] + hoff) + lane);

#pragma unroll
    for (int ic = 0; ic < 2; ic++) {
#pragma unroll
        for (int j = 0; j < 2; j++) {
            const float* p = params + (ic * 2 + j) * (KH + 1);
            float p0 = __ldg(p + 0), p1 = __ldg(p + 1), p2 = __ldg(p + 2), p3 = __ldg(p + 3);
            float4 h0 = j ? x1  : x0;
            float4 h1 = j ? h11 : h10;
            float4 h2 = j ? h21 : h20;
            float4 h3 = j ? a1  : a0;
            float4 r;
            r.x = p0 * h0.x + p1 * h1.x + p2 * h2.x + p3 * h3.x;
            r.y = p0 * h0.y + p1 * h1.y + p2 * h2.y + p3 * h3.y;
            r.z = p0 * h0.z + p1 * h1.z + p2 * h2.z + p3 * h3.z;
            r.w = p0 * h0.w + p1 * h1.w + p2 * h2.w + p3 * h3.w;
            size_t off = (size_t)gw * 256 + j * 128 + lane * 4;
            store_hilo(&g_Chi[ic][off], &g_Clo[ic][off], r);
        }
    }
}

// ---------------- cp.async double-buffered mma.sync GEMM ----------------
#define KC  32     // K elements per stage
#define SST 40     // bf16 per smem row (80 B: conflict-free ldmatrix pattern)
#define NCHUNK 24  // 768 / KC

__global__ void __launch_bounds__(256) k_gemm_mma(float* __restrict__ out) {
    const int ch = blockIdx.y;
    const int m0 = blockIdx.x * 128;

    __shared__ __nv_bfloat16 sA[2][128 * SST];
    __shared__ __nv_bfloat16 sB[2][128 * SST];

    int tid  = threadIdx.x;
    int wid  = tid >> 5;
    int lane = tid & 31;
    int wm   = (wid >> 2) * 64;
    int wn   = (wid & 3) * 32;

    const __nv_bfloat16* Bsrc = g_Bp[ch];

    // stage loader: chunk c -> stage st
    auto load_stage = [&](int c, int st) {
        int seg = c >> 3;
        int kb  = (c & 7) * KC;
        const __nv_bfloat16* Asrc = (seg == 2) ? g_Clo[ch] : g_Chi[ch];
#pragma unroll
        for (int it = 0; it < 2; it++) {
            int u     = tid + it * 256;   // 0..511
            int row   = u >> 2;
            int inner = u & 3;            // 4 x 16B per 32-elem row
            uint32_t da = smem_u32(&sA[st][row * SST + inner * 8]);
            const void* ga = Asrc + (size_t)(m0 + row) * 256 + kb + inner * 8;
            cp16(da, ga, (m0 + row < NN) ? 16 : 0);
            uint32_t db = smem_u32(&sB[st][row * SST + inner * 8]);
            const void* gb = Bsrc + (size_t)row * 768 + c * KC + inner * 8;
            cp16(db, gb, 16);
        }
        asm volatile("cp.async.commit_group;" ::: "memory");
    };

    float acc[4][4][4];
#pragma unroll
    for (int mt = 0; mt < 4; mt++)
#pragma unroll
        for (int nt = 0; nt < 4; nt++)
#pragma unroll
            for (int q = 0; q < 4; q++) acc[mt][nt][q] = 0.f;

    uint32_t aOffA = ((wm + (lane & 15)) * SST + (lane >> 4) * 8) * 2;
    uint32_t aOffB = ((wn + (lane & 7)) * SST + ((lane >> 3) & 1) * 8) * 2;

    load_stage(0, 0);

#pragma unroll 1
    for (int c = 0; c < NCHUNK; c++) {
        int st = c & 1;
        if (c + 1 < NCHUNK) {
            load_stage(c + 1, st ^ 1);
            asm volatile("cp.async.wait_group 1;" ::: "memory");
        } else {
            asm volatile("cp.async.wait_group 0;" ::: "memory");
        }
        __syncthreads();

        uint32_t aA = smem_u32(sA[st]) + aOffA;
        uint32_t aB = smem_u32(sB[st]) + aOffB;
#pragma unroll
        for (int ks = 0; ks < 2; ks++) {
            uint32_t af[4][4], bf[4][2];
#pragma unroll
            for (int mt = 0; mt < 4; mt++)
                ldsm4(af[mt], aA + (mt * 16 * SST + ks * 16) * 2);
#pragma unroll
            for (int nt = 0; nt < 4; nt++)
                ldsm2(bf[nt], aB + (nt * 8 * SST + ks * 16) * 2);
#pragma unroll
            for (int mt = 0; mt < 4; mt++)
#pragma unroll
                for (int nt = 0; nt < 4; nt++)
                    mma16816(acc[mt][nt], af[mt], bf[nt]);
        }
        __syncthreads();
    }

    // epilogue
    float* Cout = out + (size_t)ch * NN * 128;
    int r0 = lane >> 2;
    int cn = (lane & 3) * 2;
#pragma unroll
    for (int mt = 0; mt < 4; mt++) {
        int gm_a = m0 + wm + mt * 16 + r0;
        int gm_b = gm_a + 8;
#pragma unroll
        for (int nt = 0; nt < 4; nt++) {
            int gn = wn + nt * 8 + cn;
            if (gm_a < NN)
                *(float2*)&Cout[(size_t)gm_a * 128 + gn] = make_float2(acc[mt][nt][0], acc[mt][nt][1]);
            if (gm_b < NN)
                *(float2*)&Cout[(size_t)gm_b * 128 + gn] = make_float2(acc[mt][nt][2], acc[mt][nt][3]);
        }
    }
}

// ---------------- launcher ----------------
extern "C" void kernel_launch(void* const* d_in, const int* in_sizes, int n_in,
                              void* d_out, int out_size) {
    const float* x      = (const float*)d_in[0];
    const int*   ei     = (const int*)  d_in[1];
    const float* W      = (const float*)d_in[2];
    const float* params = (const float*)d_in[3];
    float* out = (float*)d_out;

    void* degPtr = nullptr;
    cudaGetSymbolAddress(&degPtr, g_deg);
    cudaMemsetAsync(degPtr, 0, NN * sizeof(int));

    k_count  <<<(NE + 255) / 256, 256>>>(ei);
    k_scan   <<<NB, 256>>>();
    k_scatter<<<(NE + 255) / 256, 256>>>(ei);
    k_wsplit <<<(2 * 128 * 768 + 255) / 256, 256>>>(W);

    k_spmm<<<(NN * 32 + 127) / 128, 128>>>(x, 0);
    k_spmm<<<(NN * 32 + 127) / 128, 128>>>(x, 1);
    k_spmm_combine<<<(NN * 32 + 127) / 128, 128>>>(x, params);

    dim3 g(NT_M, 2);
    k_gemm_mma<<<g, 256>>>(out);
}